// round 1
// baseline (speedup 1.0000x reference)
#include <cuda_runtime.h>

// Problem constants
#define NB  4        // batch
#define NN  4096     // sequence (64*64)
#define NC  128      // channels
#define ND  16       // qk head dim
#define TM  64       // query tile per CTA
#define TN  64       // key tile per iteration

typedef unsigned long long u64;

// ---- packed f32x2 helpers (Blackwell FFMA2 via PTX) ----
__device__ __forceinline__ u64 pack2(float lo, float hi) {
    u64 r; asm("mov.b64 %0, {%1, %2};" : "=l"(r) : "f"(lo), "f"(hi)); return r;
}
__device__ __forceinline__ void unpack2(u64 v, float& lo, float& hi) {
    asm("mov.b64 {%0, %1}, %2;" : "=f"(lo), "=f"(hi) : "l"(v));
}
__device__ __forceinline__ u64 fma2(u64 a, u64 b, u64 c) {
    u64 d; asm("fma.rn.f32x2 %0, %1, %2, %3;" : "=l"(d) : "l"(a), "l"(b), "l"(c)); return d;
}

// ---- scratch (device globals: no allocation allowed) ----
__device__ float g_f [NB * NN * ND];           // keys   = x @ Wq   (1 MB... 256KB)
__device__ float g_gq[NB * NN * ND];           // queries= x @ Wk
__device__ float g_hv[(size_t)NB * NN * NC];   // values = x @ Wv   (8 MB)

// =====================================================================
// Projection kernel: f = x@Wq, g = x@Wk, hv = x@Wv
// grid 256 CTAs x 256 thr; CTA handles 64 rows.
// smem: x tile [64][132], Wv [128][128], Wq [128][16], Wk [128][16]
// =====================================================================
#define XP 132                          // x smem pitch (floats) -> bank-safe broadcast
#define PROJ_SMEM_FLOATS (64*XP + 128*128 + 128*16 + 128*16)
#define PROJ_SMEM_BYTES  (PROJ_SMEM_FLOATS * 4)

__global__ __launch_bounds__(256) void proj_kernel(
        const float* __restrict__ x,
        const float* __restrict__ Wq,
        const float* __restrict__ Wk,
        const float* __restrict__ Wv) {
    extern __shared__ float sm[];
    float* x_sm  = sm;                         // 64*132
    float* wv_sm = sm + 64*XP;                 // 128*128
    float* wq_sm = wv_sm + 128*128;            // 128*16
    float* wk_sm = wq_sm + 128*16;             // 128*16

    const int t = threadIdx.x;
    const int row0 = blockIdx.x * 64;          // global flat row (b*4096+n)

    // loads
    {
        float4* d4 = (float4*)x_sm;
        const float4* s4 = (const float4*)(x + (size_t)row0 * NC);
        #pragma unroll
        for (int i = t; i < 64*32; i += 256) {
            int r = i >> 5, c = i & 31;
            d4[r*33 + c] = s4[i];              // pitch 132 floats = 33 float4
        }
    }
    {
        float4* d4 = (float4*)wv_sm; const float4* s4 = (const float4*)Wv;
        #pragma unroll
        for (int i = t; i < 128*32; i += 256) d4[i] = s4[i];
        float4* q4 = (float4*)wq_sm; const float4* qs = (const float4*)Wq;
        float4* k4 = (float4*)wk_sm; const float4* ks = (const float4*)Wk;
        #pragma unroll
        for (int i = t; i < 128*4; i += 256) { q4[i] = qs[i]; k4[i] = ks[i]; }
    }
    __syncthreads();

    const int m  = t >> 2;                      // local row 0..63
    const int q  = t & 3;
    const int c0 = q * 32;                      // hv channel slice
    const int d0 = q * 4;                       // f/g dim slice

    u64 acc[16];
    #pragma unroll
    for (int i = 0; i < 16; i++) acc[i] = pack2(0.f, 0.f);
    u64 fa0 = pack2(0.f,0.f), fa1 = fa0, ga0 = fa0, ga1 = fa0;

    #pragma unroll 4
    for (int k = 0; k < 128; k++) {
        float xv = x_sm[m*XP + k];
        u64 xp = pack2(xv, xv);
        const ulonglong2* wrow = (const ulonglong2*)(wv_sm + k*128 + c0);
        #pragma unroll
        for (int i = 0; i < 8; i++) {
            ulonglong2 w = wrow[i];
            acc[2*i]   = fma2(xp, w.x, acc[2*i]);
            acc[2*i+1] = fma2(xp, w.y, acc[2*i+1]);
        }
        ulonglong2 wq2 = *(const ulonglong2*)(wq_sm + k*16 + d0);
        fa0 = fma2(xp, wq2.x, fa0); fa1 = fma2(xp, wq2.y, fa1);
        ulonglong2 wk2 = *(const ulonglong2*)(wk_sm + k*16 + d0);
        ga0 = fma2(xp, wk2.x, ga0); ga1 = fma2(xp, wk2.y, ga1);
    }

    // write hv (coalesced at sector level)
    {
        float4* out4 = (float4*)(g_hv + (size_t)(row0 + m) * NC + c0);
        #pragma unroll
        for (int i = 0; i < 8; i++) {
            float a0,a1,a2,a3;
            unpack2(acc[2*i],   a0, a1);
            unpack2(acc[2*i+1], a2, a3);
            out4[i] = make_float4(a0, a1, a2, a3);
        }
    }
    // write f, g
    {
        float a0,a1,a2,a3;
        unpack2(fa0, a0, a1); unpack2(fa1, a2, a3);
        *(float4*)(g_f  + (size_t)(row0 + m) * ND + d0) = make_float4(a0,a1,a2,a3);
        unpack2(ga0, a0, a1); unpack2(ga1, a2, a3);
        *(float4*)(g_gq + (size_t)(row0 + m) * ND + d0) = make_float4(a0,a1,a2,a3);
    }
}

// =====================================================================
// Flash attention kernel (no max-subtraction: scores bounded ~|7|)
// grid (64 m-tiles, 4 batches) x 256 thr.
// thread = (m = t/4, tq = t%4): channels c0=tq*32, score n-chunk {tq+4j}
// smem: f tile [64][20] (pitch 20 -> conflict-free 4-row reads),
//       hv tile [64][128], p tile [64][68]
// =====================================================================
#define FP 20                         // f smem pitch (floats)
#define PP 68                         // p smem pitch (floats)
#define ATTN_SMEM_FLOATS (64*FP + TN*NC + TM*PP)
#define ATTN_SMEM_BYTES  (ATTN_SMEM_FLOATS * 4)

__global__ __launch_bounds__(256) void attn_kernel(
        const float* __restrict__ x,
        const float* __restrict__ gammap,
        float* __restrict__ out) {
    extern __shared__ float sm[];
    float* f_sm  = sm;                 // 64*20
    float* hv_sm = sm + 64*FP;         // 64*128
    float* p_sm  = hv_sm + TN*NC;      // 64*68

    const int t  = threadIdx.x;
    const int b  = blockIdx.y;
    const int m  = t >> 2;
    const int tq = t & 3;
    const int c0 = tq * 32;
    const int m_glob = blockIdx.x * TM + m;

    // query row -> packed registers (constant across tiles)
    u64 gp[8];
    {
        const float4* grow = (const float4*)(g_gq + ((size_t)b*NN + m_glob) * ND);
        float4 a = grow[0], bb = grow[1], cc = grow[2], dd = grow[3];
        gp[0]=pack2(a.x,a.y);  gp[1]=pack2(a.z,a.w);
        gp[2]=pack2(bb.x,bb.y);gp[3]=pack2(bb.z,bb.w);
        gp[4]=pack2(cc.x,cc.y);gp[5]=pack2(cc.z,cc.w);
        gp[6]=pack2(dd.x,dd.y);gp[7]=pack2(dd.z,dd.w);
    }

    u64 acc[16];
    #pragma unroll
    for (int i = 0; i < 16; i++) acc[i] = pack2(0.f, 0.f);
    float lsum = 0.f;

    const float4* fbase  = (const float4*)(g_f  + (size_t)b * NN * ND);
    const float4* hvbase = (const float4*)(g_hv + (size_t)b * NN * NC);

    for (int tile = 0; tile < NN / TN; ++tile) {
        // ---- stage f tile (pitch 20) and hv tile (contiguous) ----
        {
            int r = t >> 2, k4 = t & 3;                 // 256 float4 = full f tile
            ((float4*)f_sm)[r*5 + k4] = fbase[tile*256 + t];
            float4* d4 = (float4*)hv_sm;
            const float4* s4 = hvbase + (size_t)tile * 2048;
            #pragma unroll
            for (int i = 0; i < 8; i++) d4[t + i*256] = s4[t + i*256];
        }
        __syncthreads();

        // ---- scores + exp for my 16 keys (n = tq + 4j) ----
        #pragma unroll 4
        for (int j = 0; j < 16; ++j) {
            const int n = tq + 4*j;
            const ulonglong2* frow = (const ulonglong2*)(f_sm + n*FP);
            ulonglong2 f0 = frow[0], f1 = frow[1];
            u64 a2 = fma2(gp[0], f0.x, pack2(0.f, 0.f));
            a2 = fma2(gp[1], f0.y, a2);
            a2 = fma2(gp[2], f1.x, a2);
            a2 = fma2(gp[3], f1.y, a2);
            ulonglong2 f2v = frow[2], f3v = frow[3];
            a2 = fma2(gp[4], f2v.x, a2);
            a2 = fma2(gp[5], f2v.y, a2);
            a2 = fma2(gp[6], f3v.x, a2);
            a2 = fma2(gp[7], f3v.y, a2);
            float lo, hi; unpack2(a2, lo, hi);
            float p = __expf(lo + hi);
            lsum += p;
            p_sm[m*PP + n] = p;                          // banks (4m+tq+4j)%32: conflict-free
        }
        __syncthreads();

        // ---- PV accumulate: O[m, c0..c0+31] += p[n] * hv[n, :] ----
        {
            const float* prow = p_sm + m*PP;
            const ulonglong2* hv2 = (const ulonglong2*)hv_sm;
            #pragma unroll 4
            for (int n = 0; n < TN; ++n) {
                float pf = prow[n];
                u64 ppk = pack2(pf, pf);
                const ulonglong2* vrow = hv2 + n*32 + tq*8;
                #pragma unroll
                for (int i = 0; i < 8; i++) {
                    ulonglong2 v = vrow[i];
                    acc[2*i]   = fma2(ppk, v.x, acc[2*i]);
                    acc[2*i+1] = fma2(ppk, v.y, acc[2*i+1]);
                }
            }
        }
        __syncthreads();
    }

    // ---- finalize: combine 4 partial denominators, normalize, residual ----
    lsum += __shfl_xor_sync(0xffffffffu, lsum, 1);
    lsum += __shfl_xor_sync(0xffffffffu, lsum, 2);
    const float inv   = 1.0f / lsum;
    const float gamma = *gammap;

    // out[b, c*4096 + m_glob] = gamma*O[m,c] + x_flat[b, c*4096 + m_glob]
    const size_t obase = (size_t)b * (NN * NC) + m_glob;
    #pragma unroll
    for (int i = 0; i < 16; i++) {
        float a0, a1; unpack2(acc[i], a0, a1);
        const int c = c0 + 2*i;
        const size_t idx0 = obase + (size_t)c * NN;
        const size_t idx1 = idx0 + NN;
        out[idx0] = gamma * (a0 * inv) + x[idx0];
        out[idx1] = gamma * (a1 * inv) + x[idx1];
    }
}

// =====================================================================
extern "C" void kernel_launch(void* const* d_in, const int* in_sizes, int n_in,
                              void* d_out, int out_size) {
    (void)in_sizes; (void)n_in; (void)out_size;
    const float* x     = (const float*)d_in[0];
    const float* Wq    = (const float*)d_in[1];
    const float* Wk    = (const float*)d_in[2];
    const float* Wv    = (const float*)d_in[3];
    const float* gamma = (const float*)d_in[4];
    float* out = (float*)d_out;

    cudaFuncSetAttribute((const void*)proj_kernel,
                         cudaFuncAttributeMaxDynamicSharedMemorySize, PROJ_SMEM_BYTES);
    cudaFuncSetAttribute((const void*)attn_kernel,
                         cudaFuncAttributeMaxDynamicSharedMemorySize, ATTN_SMEM_BYTES);

    proj_kernel<<<256, 256, PROJ_SMEM_BYTES>>>(x, Wq, Wk, Wv);
    attn_kernel<<<dim3(64, 4), 256, ATTN_SMEM_BYTES>>>(x, gamma, out);
}

// round 4
// speedup vs baseline: 20.5730x; 20.5730x over previous
#include <cuda_runtime.h>
#include <cuda_bf16.h>
#include <cstdint>

// Problem constants
#define NB  4        // batch
#define NN  4096     // sequence (64*64)
#define NC  128      // channels
#define ND  16       // qk head dim

typedef unsigned long long u64;

// ---- packed f32x2 helpers (proj kernel) ----
__device__ __forceinline__ u64 pack2(float lo, float hi) {
    u64 r; asm("mov.b64 %0, {%1, %2};" : "=l"(r) : "f"(lo), "f"(hi)); return r;
}
__device__ __forceinline__ void unpack2(u64 v, float& lo, float& hi) {
    asm("mov.b64 {%0, %1}, %2;" : "=f"(lo), "=f"(hi) : "l"(v));
}
__device__ __forceinline__ u64 fma2(u64 a, u64 b, u64 c) {
    u64 d; asm("fma.rn.f32x2 %0, %1, %2, %3;" : "=l"(d) : "l"(a), "l"(b), "l"(c)); return d;
}

__device__ __forceinline__ uint32_t smem_u32(const void* p) {
    uint32_t a;
    asm("{ .reg .u64 tmp; cvta.to.shared.u64 tmp, %1; cvt.u32.u64 %0, tmp; }"
        : "=r"(a) : "l"(p));
    return a;
}

// ---- warp MMA primitives (plain PTX, valid on sm_100 non-a) ----
__device__ __forceinline__ void mma16816(float* c, const uint32_t* a,
                                         uint32_t b0, uint32_t b1) {
    asm volatile(
        "mma.sync.aligned.m16n8k16.row.col.f32.bf16.bf16.f32 "
        "{%0,%1,%2,%3}, {%4,%5,%6,%7}, {%8,%9}, {%0,%1,%2,%3};"
        : "+f"(c[0]), "+f"(c[1]), "+f"(c[2]), "+f"(c[3])
        : "r"(a[0]), "r"(a[1]), "r"(a[2]), "r"(a[3]), "r"(b0), "r"(b1));
}
#define LDSM_X4(r0,r1,r2,r3,addr) \
    asm volatile("ldmatrix.sync.aligned.m8n8.x4.shared.b16 {%0,%1,%2,%3}, [%4];" \
        : "=r"(r0), "=r"(r1), "=r"(r2), "=r"(r3) : "r"(addr))
#define LDSM_X4_T(r0,r1,r2,r3,addr) \
    asm volatile("ldmatrix.sync.aligned.m8n8.x4.trans.shared.b16 {%0,%1,%2,%3}, [%4];" \
        : "=r"(r0), "=r"(r1), "=r"(r2), "=r"(r3) : "r"(addr))

#define CP_ASYNC16(dst, src) \
    asm volatile("cp.async.cg.shared.global [%0], [%1], 16;" :: "r"(dst), "l"(src) : "memory")
#define CP_COMMIT() asm volatile("cp.async.commit_group;" ::: "memory")
#define CP_WAIT1()  asm volatile("cp.async.wait_group 1;" ::: "memory")

// =====================================================================
// Device scratch
// =====================================================================
__device__ __nv_bfloat16 g_Qb[NB * NN * ND];            // queries = x @ Wk (bf16)
__device__ __nv_bfloat16 g_Kb[NB * NN * ND];            // keys    = x @ Wq (bf16)
__device__ __nv_bfloat16 g_V [(size_t)NB * NN * NC];    // values  = x @ Wv (bf16) [b][n][c]

// =====================================================================
// Projection kernel: Qb = x@Wk, Kb = x@Wq, V = x@Wv
// grid 256 CTAs x 256 thr; CTA handles 64 flat rows (b*4096+n).
// =====================================================================
#define XP 132
#define PROJ_SMEM_FLOATS (64*XP + 128*128 + 128*16 + 128*16)
#define PROJ_SMEM_BYTES  (PROJ_SMEM_FLOATS * 4)

__global__ __launch_bounds__(256) void proj_kernel(
        const float* __restrict__ x,
        const float* __restrict__ Wq,
        const float* __restrict__ Wk,
        const float* __restrict__ Wv) {
    extern __shared__ float sm[];
    float* x_sm  = sm;                         // 64*132
    float* wv_sm = sm + 64*XP;                 // 128*128
    float* wq_sm = wv_sm + 128*128;            // 128*16
    float* wk_sm = wq_sm + 128*16;             // 128*16

    const int t = threadIdx.x;
    const int row0 = blockIdx.x * 64;

    {
        float4* d4 = (float4*)x_sm;
        const float4* s4 = (const float4*)(x + (size_t)row0 * NC);
        #pragma unroll
        for (int i = t; i < 64*32; i += 256) {
            int r = i >> 5, c = i & 31;
            d4[r*33 + c] = s4[i];
        }
    }
    {
        float4* d4 = (float4*)wv_sm; const float4* s4 = (const float4*)Wv;
        #pragma unroll
        for (int i = t; i < 128*32; i += 256) d4[i] = s4[i];
        float4* q4 = (float4*)wq_sm; const float4* qs = (const float4*)Wq;
        float4* k4 = (float4*)wk_sm; const float4* ks = (const float4*)Wk;
        #pragma unroll
        for (int i = t; i < 128*4; i += 256) { q4[i] = qs[i]; k4[i] = ks[i]; }
    }
    __syncthreads();

    const int m  = t >> 2;
    const int q  = t & 3;
    const int c0 = q * 32;
    const int d0 = q * 4;

    u64 acc[16];
    #pragma unroll
    for (int i = 0; i < 16; i++) acc[i] = pack2(0.f, 0.f);
    u64 fa0 = pack2(0.f,0.f), fa1 = fa0, ga0 = fa0, ga1 = fa0;

    #pragma unroll 4
    for (int k = 0; k < 128; k++) {
        float xv = x_sm[m*XP + k];
        u64 xp = pack2(xv, xv);
        const ulonglong2* wrow = (const ulonglong2*)(wv_sm + k*128 + c0);
        #pragma unroll
        for (int i = 0; i < 8; i++) {
            ulonglong2 w = wrow[i];
            acc[2*i]   = fma2(xp, w.x, acc[2*i]);
            acc[2*i+1] = fma2(xp, w.y, acc[2*i+1]);
        }
        ulonglong2 wq2 = *(const ulonglong2*)(wq_sm + k*16 + d0);
        fa0 = fma2(xp, wq2.x, fa0); fa1 = fma2(xp, wq2.y, fa1);
        ulonglong2 wk2 = *(const ulonglong2*)(wk_sm + k*16 + d0);
        ga0 = fma2(xp, wk2.x, ga0); ga1 = fma2(xp, wk2.y, ga1);
    }

    // write V as bf16 [b][n][c]
    {
        uint32_t vb[16];
        #pragma unroll
        for (int i = 0; i < 16; i++) {
            float a0, a1; unpack2(acc[i], a0, a1);
            asm("cvt.rn.bf16x2.f32 %0, %1, %2;" : "=r"(vb[i]) : "f"(a1), "f"(a0));
        }
        uint4* dst = (uint4*)(g_V + (size_t)(row0 + m) * NC + c0);
        #pragma unroll
        for (int k = 0; k < 4; k++)
            dst[k] = make_uint4(vb[4*k], vb[4*k+1], vb[4*k+2], vb[4*k+3]);
    }
    // write Kb (= x@Wq, keys) and Qb (= x@Wk, queries) as bf16
    {
        float a0,a1,a2,a3;
        unpack2(fa0, a0, a1); unpack2(fa1, a2, a3);
        uint2 v;
        asm("cvt.rn.bf16x2.f32 %0, %1, %2;" : "=r"(v.x) : "f"(a1), "f"(a0));
        asm("cvt.rn.bf16x2.f32 %0, %1, %2;" : "=r"(v.y) : "f"(a3), "f"(a2));
        *(uint2*)(g_Kb + (size_t)(row0 + m) * ND + d0) = v;
        unpack2(ga0, a0, a1); unpack2(ga1, a2, a3);
        asm("cvt.rn.bf16x2.f32 %0, %1, %2;" : "=r"(v.x) : "f"(a1), "f"(a0));
        asm("cvt.rn.bf16x2.f32 %0, %1, %2;" : "=r"(v.y) : "f"(a3), "f"(a2));
        *(uint2*)(g_Qb + (size_t)(row0 + m) * ND + d0) = v;
    }
}

// =====================================================================
// Flash attention via mma.sync (HMMA). CTA = 128 queries (8 warps x 16 rows),
// loop over 32 key-tiles of 128. cp.async double-buffered K/V tiles.
// SMEM: Q [128 rows x 48B pitch], K[2][128 x 48B], V[2][128 x 272B pitch]
// =====================================================================
#define QKP 48                         // Q/K smem row pitch (bytes)
#define VP  272                        // V smem row pitch (bytes)
#define SM_Q  0
#define SM_K0 6144
#define SM_V0 18432
#define K_BUF_BYTES 6144
#define V_BUF_BYTES 34816
#define ATTN_SMEM_BYTES (SM_V0 + 2*V_BUF_BYTES)   // 88064

__global__ __launch_bounds__(256, 1) void attn_mma_kernel(
        const float* __restrict__ x,
        const float* __restrict__ gammap,
        float* __restrict__ out) {
    extern __shared__ char smem[];
    const uint32_t sb = smem_u32(smem);
    const int t = threadIdx.x;
    const int w = t >> 5, lane = t & 31;
    const int b = blockIdx.y;
    const int m0 = blockIdx.x * 128;

    const __nv_bfloat16* qbase = g_Qb + (size_t)b * NN * ND;
    const __nv_bfloat16* kbase = g_Kb + (size_t)b * NN * ND;
    const __nv_bfloat16* vbase = g_V  + (size_t)b * NN * NC;

    // ---- stage Q tile [128 x 16] (pitch 48B) ----
    {
        int r = t >> 1, ch = t & 1;
        const uint4* src = (const uint4*)(qbase + (size_t)(m0 + r) * ND) + ch;
        *(uint4*)(smem + SM_Q + r * QKP + ch * 16) = *src;
    }

    // ---- prefetch tile 0 (K+V) into buffer 0 ----
    {
        int r = t >> 1, ch = t & 1;
        CP_ASYNC16(sb + SM_K0 + r * QKP + ch * 16,
                   (const char*)(kbase) + (size_t)r * 32 + ch * 16);
        #pragma unroll
        for (int i = 0; i < 8; i++) {
            int idx = t + i * 256;
            int row = idx >> 4, vch = idx & 15;
            CP_ASYNC16(sb + SM_V0 + row * VP + vch * 16,
                       (const char*)(vbase) + (size_t)row * 256 + vch * 16);
        }
    }
    CP_COMMIT();
    __syncthreads();

    // ---- Q A-fragment (constant for whole kernel) ----
    uint32_t qa[4];
    {
        uint32_t addr = sb + SM_Q + (uint32_t)(w * 16 + (lane & 15)) * QKP
                      + (uint32_t)((lane >> 4) * 16);
        LDSM_X4(qa[0], qa[1], qa[2], qa[3], addr);
    }

    // per-lane ldmatrix fragment base offsets
    const uint32_t kfrag = (uint32_t)((lane & 7) + ((lane & 16) ? 8 : 0)) * QKP
                         + (uint32_t)((lane & 8) ? 16 : 0);
    const uint32_t vfrag = (uint32_t)((lane & 7) + ((lane & 8) ? 8 : 0)) * VP
                         + (uint32_t)((lane & 16) ? 16 : 0);

    float O[16][4];
    #pragma unroll
    for (int i = 0; i < 16; i++)
        #pragma unroll
        for (int j = 0; j < 4; j++) O[i][j] = 0.f;
    float lsum0 = 0.f, lsum1 = 0.f;

    for (int tile = 0; tile < 32; ++tile) {
        // prefetch next tile into the other buffer
        if (tile < 31) {
            const int nb_ = (tile + 1) & 1;
            const size_t n0n = (size_t)(tile + 1) * 128;
            int r = t >> 1, ch = t & 1;
            CP_ASYNC16(sb + SM_K0 + nb_ * K_BUF_BYTES + r * QKP + ch * 16,
                       (const char*)(kbase) + (n0n + r) * 32 + ch * 16);
            #pragma unroll
            for (int i = 0; i < 8; i++) {
                int idx = t + i * 256;
                int row = idx >> 4, vch = idx & 15;
                CP_ASYNC16(sb + SM_V0 + nb_ * V_BUF_BYTES + row * VP + vch * 16,
                           (const char*)(vbase) + (n0n + row) * 256 + vch * 16);
            }
        }
        CP_COMMIT();
        CP_WAIT1();
        __syncthreads();

        const uint32_t kbuf = sb + SM_K0 + (tile & 1) * K_BUF_BYTES;
        const uint32_t vbuf = sb + SM_V0 + (tile & 1) * V_BUF_BYTES;

        // ---- S = Q . K^T : 16 n-tiles of 8 keys ----
        float S[16][4];
        #pragma unroll
        for (int i = 0; i < 16; i++)
            #pragma unroll
            for (int j = 0; j < 4; j++) S[i][j] = 0.f;
        #pragma unroll
        for (int ntp = 0; ntp < 8; ntp++) {
            uint32_t kb0, kb1, kb2, kb3;
            LDSM_X4(kb0, kb1, kb2, kb3, kbuf + kfrag + (uint32_t)ntp * (16 * QKP));
            mma16816(S[2*ntp],     qa, kb0, kb1);
            mma16816(S[2*ntp + 1], qa, kb2, kb3);
        }

        // ---- exp + pack into P A-fragments (register-level relayout) ----
        uint32_t pa[8][4];
        #pragma unroll
        for (int kk = 0; kk < 8; kk++) {
            float e0 = __expf(S[2*kk][0]),   e1 = __expf(S[2*kk][1]);
            float e2 = __expf(S[2*kk][2]),   e3 = __expf(S[2*kk][3]);
            float e4 = __expf(S[2*kk+1][0]), e5 = __expf(S[2*kk+1][1]);
            float e6 = __expf(S[2*kk+1][2]), e7 = __expf(S[2*kk+1][3]);
            lsum0 += e0 + e1 + e4 + e5;
            lsum1 += e2 + e3 + e6 + e7;
            asm("cvt.rn.bf16x2.f32 %0, %1, %2;" : "=r"(pa[kk][0]) : "f"(e1), "f"(e0));
            asm("cvt.rn.bf16x2.f32 %0, %1, %2;" : "=r"(pa[kk][1]) : "f"(e3), "f"(e2));
            asm("cvt.rn.bf16x2.f32 %0, %1, %2;" : "=r"(pa[kk][2]) : "f"(e5), "f"(e4));
            asm("cvt.rn.bf16x2.f32 %0, %1, %2;" : "=r"(pa[kk][3]) : "f"(e7), "f"(e6));
        }

        // ---- O += P . V : 8 c-tile pairs x 8 k-steps ----
        #pragma unroll
        for (int cp = 0; cp < 8; cp++) {
            #pragma unroll
            for (int kk = 0; kk < 8; kk++) {
                uint32_t vb0, vb1, vb2, vb3;
                LDSM_X4_T(vb0, vb1, vb2, vb3,
                          vbuf + vfrag + (uint32_t)kk * (16 * VP) + (uint32_t)cp * 32);
                mma16816(O[2*cp],     pa[kk], vb0, vb1);
                mma16816(O[2*cp + 1], pa[kk], vb2, vb3);
            }
        }
        __syncthreads();
    }

    // ---- softmax denominators: reduce across the 4-lane quad ----
    lsum0 += __shfl_xor_sync(0xffffffffu, lsum0, 1);
    lsum0 += __shfl_xor_sync(0xffffffffu, lsum0, 2);
    lsum1 += __shfl_xor_sync(0xffffffffu, lsum1, 1);
    lsum1 += __shfl_xor_sync(0xffffffffu, lsum1, 2);
    const float inv0 = 1.0f / lsum0;
    const float inv1 = 1.0f / lsum1;
    const float gamma = *gammap;

    // ---- write out[b, c*4096 + m] = gamma*O/lsum + x ----
    const int r0 = m0 + w * 16 + (lane >> 2);
    const int r1 = r0 + 8;
    const size_t bbase = (size_t)b * (NN * NC);
    #pragma unroll
    for (int nt = 0; nt < 16; nt++) {
        const int c = nt * 8 + 2 * (lane & 3);
        const size_t i00 = bbase + (size_t)c * NN + r0;
        out[i00]        = gamma * (O[nt][0] * inv0) + x[i00];
        out[i00 + NN]   = gamma * (O[nt][1] * inv0) + x[i00 + NN];
        const size_t i10 = bbase + (size_t)c * NN + r1;
        out[i10]        = gamma * (O[nt][2] * inv1) + x[i10];
        out[i10 + NN]   = gamma * (O[nt][3] * inv1) + x[i10 + NN];
    }
}

// =====================================================================
extern "C" void kernel_launch(void* const* d_in, const int* in_sizes, int n_in,
                              void* d_out, int out_size) {
    (void)in_sizes; (void)n_in; (void)out_size;
    const float* x     = (const float*)d_in[0];
    const float* Wq    = (const float*)d_in[1];
    const float* Wk    = (const float*)d_in[2];
    const float* Wv    = (const float*)d_in[3];
    const float* gamma = (const float*)d_in[4];
    float* out = (float*)d_out;

    cudaFuncSetAttribute((const void*)proj_kernel,
                         cudaFuncAttributeMaxDynamicSharedMemorySize, PROJ_SMEM_BYTES);
    cudaFuncSetAttribute((const void*)attn_mma_kernel,
                         cudaFuncAttributeMaxDynamicSharedMemorySize, ATTN_SMEM_BYTES);

    proj_kernel<<<256, 256, PROJ_SMEM_BYTES>>>(x, Wq, Wk, Wv);
    attn_mma_kernel<<<dim3(32, 4), 256, ATTN_SMEM_BYTES>>>(x, gamma, out);
}

// round 5
// speedup vs baseline: 55.1431x; 2.6804x over previous
#include <cuda_runtime.h>
#include <cuda_bf16.h>
#include <cstdint>

// Problem constants
#define NB  4        // batch
#define NN  4096     // sequence (64*64)
#define NC  128      // channels
#define ND  16       // qk head dim

__device__ __forceinline__ uint32_t smem_u32(const void* p) {
    uint32_t a;
    asm("{ .reg .u64 tmp; cvta.to.shared.u64 tmp, %1; cvt.u32.u64 %0, tmp; }"
        : "=r"(a) : "l"(p));
    return a;
}

// ---- warp MMA primitives (plain PTX, valid on sm_100 non-a) ----
__device__ __forceinline__ void mma16816(float* c, const uint32_t* a,
                                         uint32_t b0, uint32_t b1) {
    asm volatile(
        "mma.sync.aligned.m16n8k16.row.col.f32.bf16.bf16.f32 "
        "{%0,%1,%2,%3}, {%4,%5,%6,%7}, {%8,%9}, {%0,%1,%2,%3};"
        : "+f"(c[0]), "+f"(c[1]), "+f"(c[2]), "+f"(c[3])
        : "r"(a[0]), "r"(a[1]), "r"(a[2]), "r"(a[3]), "r"(b0), "r"(b1));
}
#define LDSM_X4(r0,r1,r2,r3,addr) \
    asm volatile("ldmatrix.sync.aligned.m8n8.x4.shared.b16 {%0,%1,%2,%3}, [%4];" \
        : "=r"(r0), "=r"(r1), "=r"(r2), "=r"(r3) : "r"(addr))
#define LDSM_X4_T(r0,r1,r2,r3,addr) \
    asm volatile("ldmatrix.sync.aligned.m8n8.x4.trans.shared.b16 {%0,%1,%2,%3}, [%4];" \
        : "=r"(r0), "=r"(r1), "=r"(r2), "=r"(r3) : "r"(addr))

#define CP_ASYNC16(dst, src) \
    asm volatile("cp.async.cg.shared.global [%0], [%1], 16;" :: "r"(dst), "l"(src) : "memory")
#define CP_COMMIT() asm volatile("cp.async.commit_group;" ::: "memory")
#define CP_WAIT1()  asm volatile("cp.async.wait_group 1;" ::: "memory")
#define CP_WAIT0()  asm volatile("cp.async.wait_group 0;" ::: "memory")

// =====================================================================
// Device scratch
// =====================================================================
__device__ __nv_bfloat16 g_Qb[NB * NN * ND];            // queries = x @ Wk (bf16)
__device__ __nv_bfloat16 g_Kb[NB * NN * ND];            // keys    = x @ Wq (bf16)
__device__ __nv_bfloat16 g_V [(size_t)NB * NN * NC];    // values  = x @ Wv (bf16) [b][n][c]
__device__ __nv_bfloat16 g_Wcat[160 * 128];             // W^T concat bf16: rows 0-127 Wv^T,
                                                        // 128-143 Wq^T, 144-159 Wk^T

// =====================================================================
// W-prep: g_Wcat[r][c] = W*T (bf16). 20480 elems, trivial.
// =====================================================================
__global__ void wprep_kernel(const float* __restrict__ Wq,
                             const float* __restrict__ Wk,
                             const float* __restrict__ Wv) {
    int idx = blockIdx.x * 256 + threadIdx.x;     // grid 80 x 256 = 20480
    int r = idx >> 7, c = idx & 127;
    float v;
    if (r < 128)      v = Wv[c * 128 + r];
    else if (r < 144) v = Wq[c * 16 + (r - 128)];
    else              v = Wk[c * 16 + (r - 144)];
    g_Wcat[idx] = __float2bfloat16(v);
}

// =====================================================================
// Projection GEMM (HMMA): [16384 x 128] x [128 x 160] -> V | Kb | Qb
// grid 128 CTAs x 256 thr; CTA = 128 rows x 160 cols.
// SMEM: x tile bf16 [128 rows x 272B pitch], W tile bf16 [160 x 272B]
// =====================================================================
#define PJP 272
#define PSM_X 0
#define PSM_W (128 * PJP)
#define PROJ_SMEM_BYTES (PSM_W + 160 * PJP)     // 78336

__global__ __launch_bounds__(256, 1) void proj_mma_kernel(
        const float* __restrict__ x) {
    extern __shared__ char smem[];
    const uint32_t sb = smem_u32(smem);
    const int t = threadIdx.x;
    const int w = t >> 5, lane = t & 31;
    const int row0 = blockIdx.x * 128;            // global flat row (b*4096+n)

    // ---- stage W tile via cp.async: 160 rows x 256B ----
    {
        #pragma unroll
        for (int i = 0; i < 10; i++) {
            int idx = t + i * 256;                // 0..2559
            int r = idx >> 4, ch = idx & 15;
            CP_ASYNC16(sb + PSM_W + r * PJP + ch * 16,
                       (const char*)g_Wcat + r * 256 + ch * 16);
        }
        CP_COMMIT();
    }
    // ---- stage x tile: fp32 -> bf16, 128 rows x 128 c ----
    {
        const float4* src = (const float4*)(x + (size_t)row0 * NC);
        #pragma unroll
        for (int i = 0; i < 16; i++) {
            int idx = t + i * 256;                // 0..4095
            int r = idx >> 5, ch = idx & 31;
            float4 v = src[idx];
            uint2 p;
            asm("cvt.rn.bf16x2.f32 %0, %1, %2;" : "=r"(p.x) : "f"(v.y), "f"(v.x));
            asm("cvt.rn.bf16x2.f32 %0, %1, %2;" : "=r"(p.y) : "f"(v.w), "f"(v.z));
            *(uint2*)(smem + PSM_X + r * PJP + ch * 8) = p;
        }
    }
    CP_WAIT0();
    __syncthreads();

    // ---- GEMM: each warp 16 rows x 160 cols ----
    float C[20][4];
    #pragma unroll
    for (int i = 0; i < 20; i++)
        #pragma unroll
        for (int j = 0; j < 4; j++) C[i][j] = 0.f;

    const uint32_t a_base = sb + PSM_X + (uint32_t)(w * 16 + (lane & 15)) * PJP
                          + (uint32_t)((lane >> 4) * 16);
    const uint32_t b_base = sb + PSM_W
                          + (uint32_t)((lane & 7) + ((lane & 16) ? 8 : 0)) * PJP
                          + (uint32_t)((lane & 8) ? 16 : 0);

    #pragma unroll
    for (int k = 0; k < 8; k++) {
        uint32_t a[4];
        LDSM_X4(a[0], a[1], a[2], a[3], a_base + (uint32_t)k * 32);
        #pragma unroll
        for (int np = 0; np < 10; np++) {
            uint32_t b0, b1, b2, b3;
            LDSM_X4(b0, b1, b2, b3,
                    b_base + (uint32_t)np * (16 * PJP) + (uint32_t)k * 32);
            mma16816(C[2*np],     a, b0, b1);
            mma16816(C[2*np + 1], a, b2, b3);
        }
    }

    // ---- writeback: cols 0-127 -> g_V, 128-143 -> g_Kb, 144-159 -> g_Qb ----
    const int r0 = row0 + w * 16 + (lane >> 2);
    const int r1 = r0 + 8;
    #pragma unroll
    for (int nt = 0; nt < 20; nt++) {
        const int c = nt * 8 + 2 * (lane & 3);
        uint32_t p0, p1;
        asm("cvt.rn.bf16x2.f32 %0, %1, %2;" : "=r"(p0) : "f"(C[nt][1]), "f"(C[nt][0]));
        asm("cvt.rn.bf16x2.f32 %0, %1, %2;" : "=r"(p1) : "f"(C[nt][3]), "f"(C[nt][2]));
        if (c < 128) {
            *(uint32_t*)(g_V + (size_t)r0 * NC + c) = p0;
            *(uint32_t*)(g_V + (size_t)r1 * NC + c) = p1;
        } else if (c < 144) {
            const int d = c - 128;
            *(uint32_t*)(g_Kb + (size_t)r0 * ND + d) = p0;
            *(uint32_t*)(g_Kb + (size_t)r1 * ND + d) = p1;
        } else {
            const int d = c - 144;
            *(uint32_t*)(g_Qb + (size_t)r0 * ND + d) = p0;
            *(uint32_t*)(g_Qb + (size_t)r1 * ND + d) = p1;
        }
    }
}

// =====================================================================
// Flash attention via mma.sync (HMMA). CTA = 128 queries (8 warps x 16 rows),
// loop over 32 key-tiles of 128. cp.async double-buffered K/V tiles.
// (UNCHANGED from round 4 - measured 79.5us, near mma.sync ceiling)
// =====================================================================
#define QKP 48                         // Q/K smem row pitch (bytes)
#define VP  272                        // V smem row pitch (bytes)
#define SM_Q  0
#define SM_K0 6144
#define SM_V0 18432
#define K_BUF_BYTES 6144
#define V_BUF_BYTES 34816
#define ATTN_SMEM_BYTES (SM_V0 + 2*V_BUF_BYTES)   // 88064

__global__ __launch_bounds__(256, 1) void attn_mma_kernel(
        const float* __restrict__ x,
        const float* __restrict__ gammap,
        float* __restrict__ out) {
    extern __shared__ char smem[];
    const uint32_t sb = smem_u32(smem);
    const int t = threadIdx.x;
    const int w = t >> 5, lane = t & 31;
    const int b = blockIdx.y;
    const int m0 = blockIdx.x * 128;

    const __nv_bfloat16* qbase = g_Qb + (size_t)b * NN * ND;
    const __nv_bfloat16* kbase = g_Kb + (size_t)b * NN * ND;
    const __nv_bfloat16* vbase = g_V  + (size_t)b * NN * NC;

    // ---- stage Q tile [128 x 16] (pitch 48B) ----
    {
        int r = t >> 1, ch = t & 1;
        const uint4* src = (const uint4*)(qbase + (size_t)(m0 + r) * ND) + ch;
        *(uint4*)(smem + SM_Q + r * QKP + ch * 16) = *src;
    }

    // ---- prefetch tile 0 (K+V) into buffer 0 ----
    {
        int r = t >> 1, ch = t & 1;
        CP_ASYNC16(sb + SM_K0 + r * QKP + ch * 16,
                   (const char*)(kbase) + (size_t)r * 32 + ch * 16);
        #pragma unroll
        for (int i = 0; i < 8; i++) {
            int idx = t + i * 256;
            int row = idx >> 4, vch = idx & 15;
            CP_ASYNC16(sb + SM_V0 + row * VP + vch * 16,
                       (const char*)(vbase) + (size_t)row * 256 + vch * 16);
        }
    }
    CP_COMMIT();
    __syncthreads();

    // ---- Q A-fragment (constant for whole kernel) ----
    uint32_t qa[4];
    {
        uint32_t addr = sb + SM_Q + (uint32_t)(w * 16 + (lane & 15)) * QKP
                      + (uint32_t)((lane >> 4) * 16);
        LDSM_X4(qa[0], qa[1], qa[2], qa[3], addr);
    }

    // per-lane ldmatrix fragment base offsets
    const uint32_t kfrag = (uint32_t)((lane & 7) + ((lane & 16) ? 8 : 0)) * QKP
                         + (uint32_t)((lane & 8) ? 16 : 0);
    const uint32_t vfrag = (uint32_t)((lane & 7) + ((lane & 8) ? 8 : 0)) * VP
                         + (uint32_t)((lane & 16) ? 16 : 0);

    float O[16][4];
    #pragma unroll
    for (int i = 0; i < 16; i++)
        #pragma unroll
        for (int j = 0; j < 4; j++) O[i][j] = 0.f;
    float lsum0 = 0.f, lsum1 = 0.f;

    for (int tile = 0; tile < 32; ++tile) {
        // prefetch next tile into the other buffer
        if (tile < 31) {
            const int nb_ = (tile + 1) & 1;
            const size_t n0n = (size_t)(tile + 1) * 128;
            int r = t >> 1, ch = t & 1;
            CP_ASYNC16(sb + SM_K0 + nb_ * K_BUF_BYTES + r * QKP + ch * 16,
                       (const char*)(kbase) + (n0n + r) * 32 + ch * 16);
            #pragma unroll
            for (int i = 0; i < 8; i++) {
                int idx = t + i * 256;
                int row = idx >> 4, vch = idx & 15;
                CP_ASYNC16(sb + SM_V0 + nb_ * V_BUF_BYTES + row * VP + vch * 16,
                           (const char*)(vbase) + (n0n + row) * 256 + vch * 16);
            }
        }
        CP_COMMIT();
        CP_WAIT1();
        __syncthreads();

        const uint32_t kbuf = sb + SM_K0 + (tile & 1) * K_BUF_BYTES;
        const uint32_t vbuf = sb + SM_V0 + (tile & 1) * V_BUF_BYTES;

        // ---- S = Q . K^T : 16 n-tiles of 8 keys ----
        float S[16][4];
        #pragma unroll
        for (int i = 0; i < 16; i++)
            #pragma unroll
            for (int j = 0; j < 4; j++) S[i][j] = 0.f;
        #pragma unroll
        for (int ntp = 0; ntp < 8; ntp++) {
            uint32_t kb0, kb1, kb2, kb3;
            LDSM_X4(kb0, kb1, kb2, kb3, kbuf + kfrag + (uint32_t)ntp * (16 * QKP));
            mma16816(S[2*ntp],     qa, kb0, kb1);
            mma16816(S[2*ntp + 1], qa, kb2, kb3);
        }

        // ---- exp + pack into P A-fragments (register-level relayout) ----
        uint32_t pa[8][4];
        #pragma unroll
        for (int kk = 0; kk < 8; kk++) {
            float e0 = __expf(S[2*kk][0]),   e1 = __expf(S[2*kk][1]);
            float e2 = __expf(S[2*kk][2]),   e3 = __expf(S[2*kk][3]);
            float e4 = __expf(S[2*kk+1][0]), e5 = __expf(S[2*kk+1][1]);
            float e6 = __expf(S[2*kk+1][2]), e7 = __expf(S[2*kk+1][3]);
            lsum0 += e0 + e1 + e4 + e5;
            lsum1 += e2 + e3 + e6 + e7;
            asm("cvt.rn.bf16x2.f32 %0, %1, %2;" : "=r"(pa[kk][0]) : "f"(e1), "f"(e0));
            asm("cvt.rn.bf16x2.f32 %0, %1, %2;" : "=r"(pa[kk][1]) : "f"(e3), "f"(e2));
            asm("cvt.rn.bf16x2.f32 %0, %1, %2;" : "=r"(pa[kk][2]) : "f"(e5), "f"(e4));
            asm("cvt.rn.bf16x2.f32 %0, %1, %2;" : "=r"(pa[kk][3]) : "f"(e7), "f"(e6));
        }

        // ---- O += P . V : 8 c-tile pairs x 8 k-steps ----
        #pragma unroll
        for (int cp = 0; cp < 8; cp++) {
            #pragma unroll
            for (int kk = 0; kk < 8; kk++) {
                uint32_t vb0, vb1, vb2, vb3;
                LDSM_X4_T(vb0, vb1, vb2, vb3,
                          vbuf + vfrag + (uint32_t)kk * (16 * VP) + (uint32_t)cp * 32);
                mma16816(O[2*cp],     pa[kk], vb0, vb1);
                mma16816(O[2*cp + 1], pa[kk], vb2, vb3);
            }
        }
        __syncthreads();
    }

    // ---- softmax denominators: reduce across the 4-lane quad ----
    lsum0 += __shfl_xor_sync(0xffffffffu, lsum0, 1);
    lsum0 += __shfl_xor_sync(0xffffffffu, lsum0, 2);
    lsum1 += __shfl_xor_sync(0xffffffffu, lsum1, 1);
    lsum1 += __shfl_xor_sync(0xffffffffu, lsum1, 2);
    const float inv0 = 1.0f / lsum0;
    const float inv1 = 1.0f / lsum1;
    const float gamma = *gammap;

    // ---- write out[b, c*4096 + m] = gamma*O/lsum + x ----
    const int r0 = m0 + w * 16 + (lane >> 2);
    const int r1 = r0 + 8;
    const size_t bbase = (size_t)b * (NN * NC);
    #pragma unroll
    for (int nt = 0; nt < 16; nt++) {
        const int c = nt * 8 + 2 * (lane & 3);
        const size_t i00 = bbase + (size_t)c * NN + r0;
        out[i00]        = gamma * (O[nt][0] * inv0) + x[i00];
        out[i00 + NN]   = gamma * (O[nt][1] * inv0) + x[i00 + NN];
        const size_t i10 = bbase + (size_t)c * NN + r1;
        out[i10]        = gamma * (O[nt][2] * inv1) + x[i10];
        out[i10 + NN]   = gamma * (O[nt][3] * inv1) + x[i10 + NN];
    }
}

// =====================================================================
extern "C" void kernel_launch(void* const* d_in, const int* in_sizes, int n_in,
                              void* d_out, int out_size) {
    (void)in_sizes; (void)n_in; (void)out_size;
    const float* x     = (const float*)d_in[0];
    const float* Wq    = (const float*)d_in[1];
    const float* Wk    = (const float*)d_in[2];
    const float* Wv    = (const float*)d_in[3];
    const float* gamma = (const float*)d_in[4];
    float* out = (float*)d_out;

    cudaFuncSetAttribute((const void*)proj_mma_kernel,
                         cudaFuncAttributeMaxDynamicSharedMemorySize, PROJ_SMEM_BYTES);
    cudaFuncSetAttribute((const void*)attn_mma_kernel,
                         cudaFuncAttributeMaxDynamicSharedMemorySize, ATTN_SMEM_BYTES);

    wprep_kernel<<<80, 256>>>(Wq, Wk, Wv);
    proj_mma_kernel<<<128, 256, PROJ_SMEM_BYTES>>>(x);
    attn_mma_kernel<<<dim3(32, 4), 256, ATTN_SMEM_BYTES>>>(x, gamma, out);
}

// round 6
// speedup vs baseline: 56.4095x; 1.0230x over previous
#include <cuda_runtime.h>
#include <cuda_bf16.h>
#include <cstdint>

// Problem constants
#define NB  4        // batch
#define NN  4096     // sequence (64*64)
#define NC  128      // channels
#define ND  16       // qk head dim

__device__ __forceinline__ uint32_t smem_u32(const void* p) {
    uint32_t a;
    asm("{ .reg .u64 tmp; cvta.to.shared.u64 tmp, %1; cvt.u32.u64 %0, tmp; }"
        : "=r"(a) : "l"(p));
    return a;
}

// ---- warp MMA primitives (plain PTX, valid on sm_100 non-a) ----
__device__ __forceinline__ void mma16816(float* c, const uint32_t* a,
                                         uint32_t b0, uint32_t b1) {
    asm volatile(
        "mma.sync.aligned.m16n8k16.row.col.f32.bf16.bf16.f32 "
        "{%0,%1,%2,%3}, {%4,%5,%6,%7}, {%8,%9}, {%0,%1,%2,%3};"
        : "+f"(c[0]), "+f"(c[1]), "+f"(c[2]), "+f"(c[3])
        : "r"(a[0]), "r"(a[1]), "r"(a[2]), "r"(a[3]), "r"(b0), "r"(b1));
}
#define LDSM_X4(r0,r1,r2,r3,addr) \
    asm volatile("ldmatrix.sync.aligned.m8n8.x4.shared.b16 {%0,%1,%2,%3}, [%4];" \
        : "=r"(r0), "=r"(r1), "=r"(r2), "=r"(r3) : "r"(addr))
#define LDSM_X4_T(r0,r1,r2,r3,addr) \
    asm volatile("ldmatrix.sync.aligned.m8n8.x4.trans.shared.b16 {%0,%1,%2,%3}, [%4];" \
        : "=r"(r0), "=r"(r1), "=r"(r2), "=r"(r3) : "r"(addr))

#define CP_ASYNC16(dst, src) \
    asm volatile("cp.async.cg.shared.global [%0], [%1], 16;" :: "r"(dst), "l"(src) : "memory")
#define CP_COMMIT() asm volatile("cp.async.commit_group;" ::: "memory")
#define CP_WAIT1()  asm volatile("cp.async.wait_group 1;" ::: "memory")

// =====================================================================
// Device scratch
// =====================================================================
__device__ __nv_bfloat16 g_Qb[NB * NN * ND];            // queries = x @ Wk (bf16)
__device__ __nv_bfloat16 g_Kb[NB * NN * ND];            // keys    = x @ Wq (bf16)
__device__ __nv_bfloat16 g_V [(size_t)NB * NN * NC];    // values  = x @ Wv (bf16) [b][n][c]

// =====================================================================
// Projection GEMM (HMMA): [16384 x 128] x [128 x 160] -> V | Kb | Qb
// grid 128 CTAs x 256 thr; CTA = 128 rows x 160 cols.
// W staged in NATURAL [c rows][e cols] bf16 layout (pitch 336B, odd x 16B
// => conflict-free trans-ldmatrix); B-fragments via LDSM_X4_T (the pattern
// validated by attn's PV path). No separate wprep kernel.
// SMEM: x tile bf16 [128 x 272B], W tile bf16 [128 x 336B]
// =====================================================================
#define PJP 272
#define WP  336
#define PSM_X 0
#define PSM_W (128 * PJP)
#define PROJ_SMEM_BYTES (PSM_W + 128 * WP)      // 77824

__global__ __launch_bounds__(256, 1) void proj_mma_kernel(
        const float* __restrict__ x,
        const float* __restrict__ Wq,
        const float* __restrict__ Wk,
        const float* __restrict__ Wv) {
    extern __shared__ char smem[];
    const uint32_t sb = smem_u32(smem);
    const int t = threadIdx.x;
    const int w = t >> 5, lane = t & 31;
    const int row0 = blockIdx.x * 128;            // global flat row (b*4096+n)

    // ---- stage W natural layout, fp32 -> bf16 ----
    // Wv [128c x 128e]: cols 0-127. Coalesced float4 loads; 32 lanes of a warp
    // share one c-row and write 8B each consecutively -> conflict-free.
    {
        const float4* wv4 = (const float4*)Wv;
        #pragma unroll
        for (int i = 0; i < 16; i++) {
            int idx = t + i * 256;                // 0..4095
            int c = idx >> 5, e4 = idx & 31;
            float4 v = wv4[idx];
            uint2 p;
            asm("cvt.rn.bf16x2.f32 %0, %1, %2;" : "=r"(p.x) : "f"(v.y), "f"(v.x));
            asm("cvt.rn.bf16x2.f32 %0, %1, %2;" : "=r"(p.y) : "f"(v.w), "f"(v.z));
            *(uint2*)(smem + PSM_W + c * WP + e4 * 8) = p;
        }
        // Wq [128c x 16] -> cols 128-143 ; Wk -> cols 144-159
        const float4* wq4 = (const float4*)Wq;
        const float4* wk4 = (const float4*)Wk;
        #pragma unroll
        for (int i = 0; i < 2; i++) {
            int idx = t + i * 256;                // 0..511
            int c = idx >> 2, d4 = idx & 3;
            float4 q = wq4[idx];
            uint2 p;
            asm("cvt.rn.bf16x2.f32 %0, %1, %2;" : "=r"(p.x) : "f"(q.y), "f"(q.x));
            asm("cvt.rn.bf16x2.f32 %0, %1, %2;" : "=r"(p.y) : "f"(q.w), "f"(q.z));
            *(uint2*)(smem + PSM_W + c * WP + 256 + d4 * 8) = p;
            float4 k = wk4[idx];
            asm("cvt.rn.bf16x2.f32 %0, %1, %2;" : "=r"(p.x) : "f"(k.y), "f"(k.x));
            asm("cvt.rn.bf16x2.f32 %0, %1, %2;" : "=r"(p.y) : "f"(k.w), "f"(k.z));
            *(uint2*)(smem + PSM_W + c * WP + 288 + d4 * 8) = p;
        }
    }
    // ---- stage x tile: fp32 -> bf16, 128 rows x 128 c ----
    {
        const float4* src = (const float4*)(x + (size_t)row0 * NC);
        #pragma unroll
        for (int i = 0; i < 16; i++) {
            int idx = t + i * 256;                // 0..4095
            int r = idx >> 5, ch = idx & 31;
            float4 v = src[idx];
            uint2 p;
            asm("cvt.rn.bf16x2.f32 %0, %1, %2;" : "=r"(p.x) : "f"(v.y), "f"(v.x));
            asm("cvt.rn.bf16x2.f32 %0, %1, %2;" : "=r"(p.y) : "f"(v.w), "f"(v.z));
            *(uint2*)(smem + PSM_X + r * PJP + ch * 8) = p;
        }
    }
    __syncthreads();

    // ---- GEMM: each warp 16 rows x 160 cols ----
    float C[20][4];
    #pragma unroll
    for (int i = 0; i < 20; i++)
        #pragma unroll
        for (int j = 0; j < 4; j++) C[i][j] = 0.f;

    const uint32_t a_base = sb + PSM_X + (uint32_t)(w * 16 + (lane & 15)) * PJP
                          + (uint32_t)((lane >> 4) * 16);
    // trans-fragment base (mirrors attn vfrag): row=(lane&7)+((lane&8)?8:0), +16B if lane&16
    const uint32_t b_base = sb + PSM_W
                          + (uint32_t)((lane & 7) + ((lane & 8) ? 8 : 0)) * WP
                          + (uint32_t)((lane & 16) ? 16 : 0);

    #pragma unroll
    for (int k = 0; k < 8; k++) {
        uint32_t a[4];
        LDSM_X4(a[0], a[1], a[2], a[3], a_base + (uint32_t)k * 32);
        #pragma unroll
        for (int np = 0; np < 10; np++) {
            uint32_t b0, b1, b2, b3;
            LDSM_X4_T(b0, b1, b2, b3,
                      b_base + (uint32_t)k * (16 * WP) + (uint32_t)np * 32);
            mma16816(C[2*np],     a, b0, b1);
            mma16816(C[2*np + 1], a, b2, b3);
        }
    }

    // ---- writeback: cols 0-127 -> g_V, 128-143 -> g_Kb, 144-159 -> g_Qb ----
    const int r0 = row0 + w * 16 + (lane >> 2);
    const int r1 = r0 + 8;
    #pragma unroll
    for (int nt = 0; nt < 20; nt++) {
        const int c = nt * 8 + 2 * (lane & 3);
        uint32_t p0, p1;
        asm("cvt.rn.bf16x2.f32 %0, %1, %2;" : "=r"(p0) : "f"(C[nt][1]), "f"(C[nt][0]));
        asm("cvt.rn.bf16x2.f32 %0, %1, %2;" : "=r"(p1) : "f"(C[nt][3]), "f"(C[nt][2]));
        if (c < 128) {
            *(uint32_t*)(g_V + (size_t)r0 * NC + c) = p0;
            *(uint32_t*)(g_V + (size_t)r1 * NC + c) = p1;
        } else if (c < 144) {
            const int d = c - 128;
            *(uint32_t*)(g_Kb + (size_t)r0 * ND + d) = p0;
            *(uint32_t*)(g_Kb + (size_t)r1 * ND + d) = p1;
        } else {
            const int d = c - 144;
            *(uint32_t*)(g_Qb + (size_t)r0 * ND + d) = p0;
            *(uint32_t*)(g_Qb + (size_t)r1 * ND + d) = p1;
        }
    }
}

// =====================================================================
// Flash attention via mma.sync (HMMA). CTA = 128 queries (8 warps x 16 rows),
// loop over 32 key-tiles of 128. cp.async double-buffered K/V tiles.
// PV loop: kk OUTER / cp INNER -> 16 independent accumulator chains per step
// (round 5 had cp outer: 8-deep serial HMMA chains per accumulator).
// =====================================================================
#define QKP 48                         // Q/K smem row pitch (bytes)
#define VP  272                        // V smem row pitch (bytes)
#define SM_Q  0
#define SM_K0 6144
#define SM_V0 18432
#define K_BUF_BYTES 6144
#define V_BUF_BYTES 34816
#define ATTN_SMEM_BYTES (SM_V0 + 2*V_BUF_BYTES)   // 88064

__global__ __launch_bounds__(256, 1) void attn_mma_kernel(
        const float* __restrict__ x,
        const float* __restrict__ gammap,
        float* __restrict__ out) {
    extern __shared__ char smem[];
    const uint32_t sb = smem_u32(smem);
    const int t = threadIdx.x;
    const int w = t >> 5, lane = t & 31;
    const int b = blockIdx.y;
    const int m0 = blockIdx.x * 128;

    const __nv_bfloat16* qbase = g_Qb + (size_t)b * NN * ND;
    const __nv_bfloat16* kbase = g_Kb + (size_t)b * NN * ND;
    const __nv_bfloat16* vbase = g_V  + (size_t)b * NN * NC;

    // ---- stage Q tile [128 x 16] (pitch 48B) ----
    {
        int r = t >> 1, ch = t & 1;
        const uint4* src = (const uint4*)(qbase + (size_t)(m0 + r) * ND) + ch;
        *(uint4*)(smem + SM_Q + r * QKP + ch * 16) = *src;
    }

    // ---- prefetch tile 0 (K+V) into buffer 0 ----
    {
        int r = t >> 1, ch = t & 1;
        CP_ASYNC16(sb + SM_K0 + r * QKP + ch * 16,
                   (const char*)(kbase) + (size_t)r * 32 + ch * 16);
        #pragma unroll
        for (int i = 0; i < 8; i++) {
            int idx = t + i * 256;
            int row = idx >> 4, vch = idx & 15;
            CP_ASYNC16(sb + SM_V0 + row * VP + vch * 16,
                       (const char*)(vbase) + (size_t)row * 256 + vch * 16);
        }
    }
    CP_COMMIT();
    __syncthreads();

    // ---- Q A-fragment (constant for whole kernel) ----
    uint32_t qa[4];
    {
        uint32_t addr = sb + SM_Q + (uint32_t)(w * 16 + (lane & 15)) * QKP
                      + (uint32_t)((lane >> 4) * 16);
        LDSM_X4(qa[0], qa[1], qa[2], qa[3], addr);
    }

    // per-lane ldmatrix fragment base offsets
    const uint32_t kfrag = (uint32_t)((lane & 7) + ((lane & 16) ? 8 : 0)) * QKP
                         + (uint32_t)((lane & 8) ? 16 : 0);
    const uint32_t vfrag = (uint32_t)((lane & 7) + ((lane & 8) ? 8 : 0)) * VP
                         + (uint32_t)((lane & 16) ? 16 : 0);

    float O[16][4];
    #pragma unroll
    for (int i = 0; i < 16; i++)
        #pragma unroll
        for (int j = 0; j < 4; j++) O[i][j] = 0.f;
    float lsum0 = 0.f, lsum1 = 0.f;

    for (int tile = 0; tile < 32; ++tile) {
        // prefetch next tile into the other buffer
        if (tile < 31) {
            const int nb_ = (tile + 1) & 1;
            const size_t n0n = (size_t)(tile + 1) * 128;
            int r = t >> 1, ch = t & 1;
            CP_ASYNC16(sb + SM_K0 + nb_ * K_BUF_BYTES + r * QKP + ch * 16,
                       (const char*)(kbase) + (n0n + r) * 32 + ch * 16);
            #pragma unroll
            for (int i = 0; i < 8; i++) {
                int idx = t + i * 256;
                int row = idx >> 4, vch = idx & 15;
                CP_ASYNC16(sb + SM_V0 + nb_ * V_BUF_BYTES + row * VP + vch * 16,
                           (const char*)(vbase) + (n0n + row) * 256 + vch * 16);
            }
        }
        CP_COMMIT();
        CP_WAIT1();
        __syncthreads();

        const uint32_t kbuf = sb + SM_K0 + (tile & 1) * K_BUF_BYTES;
        const uint32_t vbuf = sb + SM_V0 + (tile & 1) * V_BUF_BYTES;

        // ---- S = Q . K^T : 16 n-tiles of 8 keys ----
        float S[16][4];
        #pragma unroll
        for (int i = 0; i < 16; i++)
            #pragma unroll
            for (int j = 0; j < 4; j++) S[i][j] = 0.f;
        #pragma unroll
        for (int ntp = 0; ntp < 8; ntp++) {
            uint32_t kb0, kb1, kb2, kb3;
            LDSM_X4(kb0, kb1, kb2, kb3, kbuf + kfrag + (uint32_t)ntp * (16 * QKP));
            mma16816(S[2*ntp],     qa, kb0, kb1);
            mma16816(S[2*ntp + 1], qa, kb2, kb3);
        }

        // ---- exp + pack into P A-fragments (register-level relayout) ----
        uint32_t pa[8][4];
        #pragma unroll
        for (int kk = 0; kk < 8; kk++) {
            float e0 = __expf(S[2*kk][0]),   e1 = __expf(S[2*kk][1]);
            float e2 = __expf(S[2*kk][2]),   e3 = __expf(S[2*kk][3]);
            float e4 = __expf(S[2*kk+1][0]), e5 = __expf(S[2*kk+1][1]);
            float e6 = __expf(S[2*kk+1][2]), e7 = __expf(S[2*kk+1][3]);
            lsum0 += e0 + e1 + e4 + e5;
            lsum1 += e2 + e3 + e6 + e7;
            asm("cvt.rn.bf16x2.f32 %0, %1, %2;" : "=r"(pa[kk][0]) : "f"(e1), "f"(e0));
            asm("cvt.rn.bf16x2.f32 %0, %1, %2;" : "=r"(pa[kk][1]) : "f"(e3), "f"(e2));
            asm("cvt.rn.bf16x2.f32 %0, %1, %2;" : "=r"(pa[kk][2]) : "f"(e5), "f"(e4));
            asm("cvt.rn.bf16x2.f32 %0, %1, %2;" : "=r"(pa[kk][3]) : "f"(e7), "f"(e6));
        }

        // ---- O += P . V : kk OUTER, cp INNER (16 independent chains/step) ----
        #pragma unroll
        for (int kk = 0; kk < 8; kk++) {
            #pragma unroll
            for (int cp = 0; cp < 8; cp++) {
                uint32_t vb0, vb1, vb2, vb3;
                LDSM_X4_T(vb0, vb1, vb2, vb3,
                          vbuf + vfrag + (uint32_t)kk * (16 * VP) + (uint32_t)cp * 32);
                mma16816(O[2*cp],     pa[kk], vb0, vb1);
                mma16816(O[2*cp + 1], pa[kk], vb2, vb3);
            }
        }
        __syncthreads();
    }

    // ---- softmax denominators: reduce across the 4-lane quad ----
    lsum0 += __shfl_xor_sync(0xffffffffu, lsum0, 1);
    lsum0 += __shfl_xor_sync(0xffffffffu, lsum0, 2);
    lsum1 += __shfl_xor_sync(0xffffffffu, lsum1, 1);
    lsum1 += __shfl_xor_sync(0xffffffffu, lsum1, 2);
    const float inv0 = 1.0f / lsum0;
    const float inv1 = 1.0f / lsum1;
    const float gamma = *gammap;

    // ---- write out[b, c*4096 + m] = gamma*O/lsum + x ----
    const int r0 = m0 + w * 16 + (lane >> 2);
    const int r1 = r0 + 8;
    const size_t bbase = (size_t)b * (NN * NC);
    #pragma unroll
    for (int nt = 0; nt < 16; nt++) {
        const int c = nt * 8 + 2 * (lane & 3);
        const size_t i00 = bbase + (size_t)c * NN + r0;
        out[i00]        = gamma * (O[nt][0] * inv0) + x[i00];
        out[i00 + NN]   = gamma * (O[nt][1] * inv0) + x[i00 + NN];
        const size_t i10 = bbase + (size_t)c * NN + r1;
        out[i10]        = gamma * (O[nt][2] * inv1) + x[i10];
        out[i10 + NN]   = gamma * (O[nt][3] * inv1) + x[i10 + NN];
    }
}

// =====================================================================
extern "C" void kernel_launch(void* const* d_in, const int* in_sizes, int n_in,
                              void* d_out, int out_size) {
    (void)in_sizes; (void)n_in; (void)out_size;
    const float* x     = (const float*)d_in[0];
    const float* Wq    = (const float*)d_in[1];
    const float* Wk    = (const float*)d_in[2];
    const float* Wv    = (const float*)d_in[3];
    const float* gamma = (const float*)d_in[4];
    float* out = (float*)d_out;

    cudaFuncSetAttribute((const void*)proj_mma_kernel,
                         cudaFuncAttributeMaxDynamicSharedMemorySize, PROJ_SMEM_BYTES);
    cudaFuncSetAttribute((const void*)attn_mma_kernel,
                         cudaFuncAttributeMaxDynamicSharedMemorySize, ATTN_SMEM_BYTES);

    proj_mma_kernel<<<128, 256, PROJ_SMEM_BYTES>>>(x, Wq, Wk, Wv);
    attn_mma_kernel<<<dim3(32, 4), 256, ATTN_SMEM_BYTES>>>(x, gamma, out);
}